// round 4
// baseline (speedup 1.0000x reference)
#include <cuda_runtime.h>
#include <cuda_bf16.h>
#include <cstdint>

#define DIN 1024
#define DH  256
#define NC  8
#define NMAX 65536

#define BM 128
#define BN 256
#define BK 128
#define NT 512
#define CHUNKS (DIN / BK)   // 8
#define SPS 264

// ---------------- device scratch ----------------
__device__ float g_csum[NC * DH];
__device__ int   g_cnt[NC];
__device__ int   g_off[NC];
__device__ int   g_perm[NMAX];
__device__ int   g_scid[NMAX];
__device__ __align__(16) __nv_bfloat16 g_w1bf[DH * DIN];

// ---------------- helpers ----------------
__device__ __forceinline__ uint32_t smem_to_u32(const void* p) {
    uint32_t a;
    asm("{ .reg .u64 t; cvta.to.shared.u64 t, %1; cvt.u32.u64 %0, t; }"
        : "=r"(a) : "l"(p));
    return a;
}
#define CP_ASYNC16(dst, src) \
    asm volatile("cp.async.cg.shared.global [%0], [%1], 16;" :: "r"(dst), "l"(src) : "memory")
#define CP_COMMIT() asm volatile("cp.async.commit_group;" ::: "memory")
#define CP_WAIT0()  asm volatile("cp.async.wait_group 0;" ::: "memory")
#define LDSM4(r0, r1, r2, r3, a) \
    asm volatile("ldmatrix.sync.aligned.m8n8.x4.shared.b16 {%0,%1,%2,%3}, [%4];" \
                 : "=r"(r0), "=r"(r1), "=r"(r2), "=r"(r3) : "r"(a))
#define MMA16816(d0,d1,d2,d3, a0,a1,a2,a3, b0,b1) \
    asm volatile("mma.sync.aligned.m16n8k16.row.col.f32.bf16.bf16.f32 " \
                 "{%0,%1,%2,%3}, {%4,%5,%6,%7}, {%8,%9}, {%0,%1,%2,%3};\n" \
                 : "+f"(d0), "+f"(d1), "+f"(d2), "+f"(d3) \
                 : "r"(a0), "r"(a1), "r"(a2), "r"(a3), "r"(b0), "r"(b1))

// ---------------- k_prep: W1->bf16 (blocks 0..255) + cluster count (256..383) ----------------
__global__ void k_prep(const float* __restrict__ W1, const int* __restrict__ cid, int n) {
    if (blockIdx.x < 256) {
        int base = blockIdx.x * 1024 + threadIdx.x;
#pragma unroll
        for (int t = 0; t < 4; t++) {
            int i = base + t * 256;
            g_w1bf[i] = __float2bfloat16(W1[i]);
        }
    } else {
        __shared__ int h[NC];
        if (threadIdx.x < NC) h[threadIdx.x] = 0;
        __syncthreads();
        int b = blockIdx.x - 256;
        for (int i = b * 256 + threadIdx.x; i < n; i += 128 * 256)
            atomicAdd(&h[cid[i]], 1);
        __syncthreads();
        if (threadIdx.x < NC) atomicAdd(&g_cnt[threadIdx.x], h[threadIdx.x]);
    }
}

__global__ void k_prefix() {
    if (threadIdx.x == 0) {
        int s = 0;
        for (int c = 0; c < NC; c++) { g_off[c] = s; s += g_cnt[c]; }
    }
}

__global__ void k_scatter(const int* __restrict__ cid, int n) {
    __shared__ int lh[NC], base[NC], lr[NC];
    int i = blockIdx.x * 256 + threadIdx.x;
    int c = (i < n) ? cid[i] : -1;
    if (threadIdx.x < NC) { lh[threadIdx.x] = 0; lr[threadIdx.x] = 0; }
    __syncthreads();
    if (c >= 0) atomicAdd(&lh[c], 1);
    __syncthreads();
    if (threadIdx.x < NC && lh[threadIdx.x] > 0)
        base[threadIdx.x] = atomicAdd(&g_off[threadIdx.x], lh[threadIdx.x]);
    __syncthreads();
    if (c >= 0) {
        int r = atomicAdd(&lr[c], 1);
        int slot = base[c] + r;
        g_perm[slot] = i;
        g_scid[slot] = c;
    }
}

// ---------------- k_main: mma.sync GEMM + ReLU + segment-sum ----------------
// smem layout (bytes); 256B rows, XOR-16B swizzle within 128B halves
#define OFF_B1S  0
#define OFF_CIDS 1024
#define OFF_PERM 1536
#define OFF_SPRT 2048       // 8448 bytes -> ends 10496
#define OFF_A    12288      // 2 stages x 32768
#define OFF_B    77824      // 2 stages x 65536
#define A_STAGE  32768
#define B_STAGE  65536
#define SMEM_BYTES 208896

__global__ __launch_bounds__(NT, 1)
void k_main(const float* __restrict__ X, const float* __restrict__ b1, int n)
{
    extern __shared__ __align__(1024) char smem[];
    const uint32_t sb = smem_to_u32(smem);
    const int tid  = threadIdx.x;
    const int lane = tid & 31;
    const int wid  = tid >> 5;
    const int wm   = wid & 3;      // 4 warps along M (32 rows)
    const int wn   = wid >> 2;     // 4 warps along N (64 cols)
    const int rowBase = blockIdx.x * BM;

    float* b1s   = (float*)(smem + OFF_B1S);
    int*   cids  = (int*)(smem + OFF_CIDS);
    int*   perms = (int*)(smem + OFF_PERM);
    float* spart = (float*)(smem + OFF_SPRT);

    for (int i = tid; i < NC * SPS; i += NT) spart[i] = 0.f;
    if (tid < DH) b1s[tid] = b1[tid];
    if (tid < BM) {
        int g = rowBase + tid;
        perms[tid] = (g < n) ? g_perm[g] : 0;
        cids[tid]  = (g < n) ? g_scid[g] : 0;
    }
    __syncthreads();

    // ---- X load map: 4 threads/row, 32 floats each ----
    const int xrow = tid >> 2;
    const int xseg = tid & 3;
    const bool xvalid = (rowBase + xrow) < n;
    const float* xsrc0 = X + (size_t)perms[xrow] * DIN + xseg * 32;
    uint32_t xdstq[4];
#pragma unroll
    for (int q = 0; q < 4; q++) {
        int c16 = xseg * 4 + q;
        xdstq[q] = sb + OFF_A + xrow * 256 + ((c16 >> 3) << 7)
                 + (((c16 & 7) ^ (xrow & 7)) << 4);
    }

    // ---- W load map: 2 threads/row, 128B each via cp.async ----
    const int wrow = tid >> 1;
    const int wseg = tid & 1;
    const char* wsrc0 = (const char*)(g_w1bf + (size_t)wrow * DIN) + wseg * 128;
    uint32_t wdstq[8];
#pragma unroll
    for (int q = 0; q < 8; q++)
        wdstq[q] = sb + OFF_B + wrow * 256 + wseg * 128
                 + ((q ^ (wrow & 7)) << 4);

    // ---- ldmatrix pointers ----
    uint32_t aPtr[2], bPtr[4];
    {
        int jm  = lane & 7;
        int sel8 = (lane >> 3) & 1;
        int selk = (lane >> 4) & 1;
#pragma unroll
        for (int mt = 0; mt < 2; mt++) {
            int r = wm * 32 + mt * 16 + jm + sel8 * 8;
            aPtr[mt] = sb + OFF_A + r * 256 + ((selk ^ (r & 1)) << 4)
                     + (((r >> 1) & 3) << 5);
        }
        int jn   = lane & 7;
        int selk2 = (lane >> 3) & 1;
        int seln  = (lane >> 4) & 1;
#pragma unroll
        for (int p = 0; p < 4; p++) {
            int r = wn * 64 + p * 16 + jn + seln * 8;
            bPtr[p] = sb + OFF_B + r * 256 + ((selk2 ^ (r & 1)) << 4)
                    + (((r >> 1) & 3) << 5);
        }
    }

    float acc[2][8][4];
#pragma unroll
    for (int a = 0; a < 2; a++)
#pragma unroll
        for (int b = 0; b < 8; b++)
#pragma unroll
            for (int c = 0; c < 4; c++) acc[a][b][c] = 0.f;

    auto ldx = [&](int chunk, uint32_t h[16]) {
        const float4* p = (const float4*)(xsrc0 + chunk * BK);
#pragma unroll
        for (int t = 0; t < 8; t++) {
            float4 f = xvalid ? p[t] : make_float4(0.f, 0.f, 0.f, 0.f);
            __nv_bfloat162 lo = __floats2bfloat162_rn(f.x, f.y);
            __nv_bfloat162 hi = __floats2bfloat162_rn(f.z, f.w);
            h[t * 2]     = *(uint32_t*)&lo;
            h[t * 2 + 1] = *(uint32_t*)&hi;
        }
    };
    auto stx = [&](int stage, const uint32_t h[16]) {
#pragma unroll
        for (int q = 0; q < 4; q++) {
            uint32_t d = xdstq[q] + stage * A_STAGE;
            asm volatile("st.shared.v4.b32 [%0], {%1,%2,%3,%4};" ::
                         "r"(d), "r"(h[q*4]), "r"(h[q*4+1]),
                         "r"(h[q*4+2]), "r"(h[q*4+3]) : "memory");
        }
    };
    auto ldw = [&](int chunk, int stage) {
        const char* s = wsrc0 + chunk * 256;
#pragma unroll
        for (int q = 0; q < 8; q++)
            CP_ASYNC16(wdstq[q] + stage * B_STAGE, s + q * 16);
        CP_COMMIT();
    };

    auto compute = [&](int stage) {
        const uint32_t aOfs = stage * A_STAGE;
        const uint32_t bOfs = stage * B_STAGE;
#pragma unroll
        for (int kk = 0; kk < 8; kk++) {
            const uint32_t xr = (uint32_t)((kk & 3) << 5);
            const uint32_t ad = (uint32_t)((kk >> 2) << 7);
            uint32_t af[2][4];
#pragma unroll
            for (int mt = 0; mt < 2; mt++)
                LDSM4(af[mt][0], af[mt][1], af[mt][2], af[mt][3],
                      (aPtr[mt] + aOfs + ad) ^ xr);
            uint32_t bf[4][4];
#pragma unroll
            for (int p = 0; p < 4; p++)
                LDSM4(bf[p][0], bf[p][1], bf[p][2], bf[p][3],
                      (bPtr[p] + bOfs + ad) ^ xr);
#pragma unroll
            for (int mt = 0; mt < 2; mt++)
#pragma unroll
                for (int p = 0; p < 4; p++) {
                    MMA16816(acc[mt][2*p][0],   acc[mt][2*p][1],
                             acc[mt][2*p][2],   acc[mt][2*p][3],
                             af[mt][0], af[mt][1], af[mt][2], af[mt][3],
                             bf[p][0], bf[p][1]);
                    MMA16816(acc[mt][2*p+1][0], acc[mt][2*p+1][1],
                             acc[mt][2*p+1][2], acc[mt][2*p+1][3],
                             af[mt][0], af[mt][1], af[mt][2], af[mt][3],
                             bf[p][2], bf[p][3]);
                }
        }
    };

    // ---- prologue ----
    {
        uint32_t h0[16];
        ldw(0, 0);
        ldx(0, h0);
        stx(0, h0);
    }

    // ---- main loop (double-buffered, 8 chunks) ----
    for (int chunk = 0; chunk < CHUNKS; chunk++) {
        const int cur = chunk & 1;
        const int nxt = cur ^ 1;
        const bool more = (chunk + 1) < CHUNKS;
        uint32_t h2[16];
        if (more) ldx(chunk + 1, h2);
        CP_WAIT0();
        __syncthreads();
        if (more) {
            ldw(chunk + 1, nxt);
            stx(nxt, h2);
        }
        compute(cur);
    }

    // ---- epilogue: bias + ReLU + segment-sum ----
    const int g  = lane >> 2;
    const int tg = lane & 3;
    const bool uni = (cids[0] == cids[BM - 1]) && (rowBase + BM <= n);

    if (uni) {
        const int cl = cids[0];
#pragma unroll
        for (int nt = 0; nt < 8; nt++) {
            int c = wn * 64 + nt * 8 + tg * 2;
            float s0 = 0.f, s1 = 0.f;
#pragma unroll
            for (int mt = 0; mt < 2; mt++) {
                s0 += fmaxf(acc[mt][nt][0] + b1s[c], 0.f)
                    + fmaxf(acc[mt][nt][2] + b1s[c], 0.f);
                s1 += fmaxf(acc[mt][nt][1] + b1s[c + 1], 0.f)
                    + fmaxf(acc[mt][nt][3] + b1s[c + 1], 0.f);
            }
#pragma unroll
            for (int o = 4; o < 32; o <<= 1) {
                s0 += __shfl_xor_sync(0xffffffffu, s0, o);
                s1 += __shfl_xor_sync(0xffffffffu, s1, o);
            }
            if (g == 0) {
                atomicAdd(&spart[cl * SPS + c], s0);
                atomicAdd(&spart[cl * SPS + c + 1], s1);
            }
        }
    } else {
#pragma unroll
        for (int mt = 0; mt < 2; mt++) {
            int r0 = wm * 32 + mt * 16 + g;
            int r1 = r0 + 8;
            bool v0 = (rowBase + r0) < n;
            bool v1 = (rowBase + r1) < n;
            int c0 = cids[r0] * SPS;
            int c1 = cids[r1] * SPS;
#pragma unroll
            for (int nt = 0; nt < 8; nt++) {
                int c = wn * 64 + nt * 8 + tg * 2;
                float t;
                t = acc[mt][nt][0] + b1s[c];
                if (v0 && t > 0.f) atomicAdd(&spart[c0 + c], t);
                t = acc[mt][nt][1] + b1s[c + 1];
                if (v0 && t > 0.f) atomicAdd(&spart[c0 + c + 1], t);
                t = acc[mt][nt][2] + b1s[c];
                if (v1 && t > 0.f) atomicAdd(&spart[c1 + c], t);
                t = acc[mt][nt][3] + b1s[c + 1];
                if (v1 && t > 0.f) atomicAdd(&spart[c1 + c + 1], t);
            }
        }
    }
    __syncthreads();
    for (int i = tid; i < NC * DH; i += NT) {
        int c = i >> 8, j = i & 255;
        float v = spart[c * SPS + j];
        if (v != 0.f) atomicAdd(&g_csum[i], v);
    }
}

// ---------------- k_final: small MLP + gated attention ----------------
__global__ __launch_bounds__(512) void k_final(
    const float* __restrict__ Wf, const float* __restrict__ bfv,
    const float* __restrict__ Wa, const float* __restrict__ ba,
    const float* __restrict__ Wb, const float* __restrict__ bb,
    const float* __restrict__ Wc, const float* __restrict__ bc,
    float* __restrict__ out)
{
    __shared__ float hc[NC][DH];
    __shared__ float hp[NC][DH];
    __shared__ float pA[NC][DH];
    __shared__ float pB[NC][DH];
    __shared__ float asum[NC], wts[NC];

    const int tid = threadIdx.x;
    const int j = tid & 255;
    const int hf = tid >> 8;
    const int lane = tid & 31;

    for (int i = tid; i < NC * DH; i += 512) {
        int c = i >> 8;
        hc[c][i & 255] = g_csum[i] / fmaxf((float)g_cnt[c], 1.f);
    }
    if (tid < NC) asum[tid] = 0.f;
    __syncthreads();

    {
        float p[NC];
#pragma unroll
        for (int c = 0; c < NC; c++) p[c] = 0.f;
        const float4* wrow = (const float4*)(Wf + j * DH + hf * 128);
#pragma unroll 4
        for (int k4 = 0; k4 < 32; k4++) {
            float4 w = wrow[k4];
            int k = hf * 128 + k4 * 4;
#pragma unroll
            for (int c = 0; c < NC; c++) {
                float4 h4 = *(const float4*)&hc[c][k];
                p[c] += w.x * h4.x + w.y * h4.y + w.z * h4.z + w.w * h4.w;
            }
        }
        float* dst = hf ? &pB[0][0] : &pA[0][0];
#pragma unroll
        for (int c = 0; c < NC; c++) dst[c * DH + j] = p[c];
    }
    __syncthreads();

    float hpj[NC];
    if (hf == 0) {
#pragma unroll
        for (int c = 0; c < NC; c++) {
            hpj[c] = fmaxf(pA[c][j] + pB[c][j] + bfv[j], 0.f);
            hp[c][j] = hpj[c];
        }
    }
    __syncthreads();

    {
        const float* w2 = (hf ? Wb : Wa) + j * DH;
        float q[NC];
#pragma unroll
        for (int c = 0; c < NC; c++) q[c] = 0.f;
#pragma unroll 4
        for (int k4 = 0; k4 < 64; k4++) {
            float4 w = ((const float4*)w2)[k4];
#pragma unroll
            for (int c = 0; c < NC; c++) {
                float4 h4 = *(const float4*)&hp[c][k4 * 4];
                q[c] += w.x * h4.x + w.y * h4.y + w.z * h4.z + w.w * h4.w;
            }
        }
        float* dst = hf ? &pB[0][0] : &pA[0][0];
#pragma unroll
        for (int c = 0; c < NC; c++) dst[c * DH + j] = q[c];
    }
    __syncthreads();

    if (hf == 0) {
        float wcj = Wc[j];
#pragma unroll
        for (int c = 0; c < NC; c++) {
            float av = tanhf(pA[c][j] + ba[j]);
            float gv = 1.f / (1.f + __expf(-(pB[c][j] + bb[j])));
            float v = av * gv * wcj;
#pragma unroll
            for (int o = 16; o > 0; o >>= 1)
                v += __shfl_xor_sync(0xffffffffu, v, o);
            if (lane == 0) atomicAdd(&asum[c], v);
        }
    }
    __syncthreads();

    if (tid == 0) {
        float m = -1e30f;
        for (int c = 0; c < NC; c++) m = fmaxf(m, asum[c] + bc[0]);
        float s = 0.f;
        for (int c = 0; c < NC; c++) { wts[c] = __expf(asum[c] + bc[0] - m); s += wts[c]; }
        float inv = 1.f / s;
        for (int c = 0; c < NC; c++) wts[c] *= inv;
    }
    __syncthreads();

    if (hf == 0) {
        float s = 0.f;
#pragma unroll
        for (int c = 0; c < NC; c++) s += wts[c] * hpj[c];
        out[j] = s;
    }
}

// ---------------- launch ----------------
extern "C" void kernel_launch(void* const* d_in, const int* in_sizes, int n_in,
                              void* d_out, int out_size)
{
    const float* X   = (const float*)d_in[0];
    const int*   cid = (const int*)d_in[1];
    const float* W1  = (const float*)d_in[2];
    const float* b1  = (const float*)d_in[3];
    const float* Wf  = (const float*)d_in[4];
    const float* bfv = (const float*)d_in[5];
    const float* Wa  = (const float*)d_in[6];
    const float* ba  = (const float*)d_in[7];
    const float* Wb  = (const float*)d_in[8];
    const float* bb  = (const float*)d_in[9];
    const float* Wc  = (const float*)d_in[10];
    const float* bc  = (const float*)d_in[11];
    float* out = (float*)d_out;
    const int n = in_sizes[1];

    cudaFuncSetAttribute(k_main, cudaFuncAttributeMaxDynamicSharedMemorySize, SMEM_BYTES);

    void *p_csum = nullptr, *p_cnt = nullptr;
    cudaGetSymbolAddress(&p_csum, g_csum);
    cudaGetSymbolAddress(&p_cnt,  g_cnt);
    cudaMemsetAsync(p_csum, 0, sizeof(float) * NC * DH, 0);    // launch 1
    cudaMemsetAsync(p_cnt,  0, sizeof(int) * NC, 0);           // launch 2

    k_prep<<<384, 256>>>(W1, cid, n);                          // launch 3
    k_prefix<<<1, 32>>>();                                     // launch 4
    int sg = (n + 255) / 256;
    k_scatter<<<sg, 256>>>(cid, n);                            // launch 5

    int grid = (n + BM - 1) / BM;
    k_main<<<grid, NT, SMEM_BYTES>>>(X, b1, n);                // launch 6 (profiled)
    k_final<<<1, 512>>>(Wf, bfv, Wa, ba, Wb, bb, Wc, bc, out); // launch 7
}

// round 5
// speedup vs baseline: 1.2916x; 1.2916x over previous
#include <cuda_runtime.h>
#include <cuda_bf16.h>
#include <cstdint>

#define DIN 1024
#define DH  256
#define NC  8
#define NMAX 65536

#define BM 128
#define BN 256
#define BK 64
#define NT 512
#define CHUNKS (DIN / BK)   // 16
#define SPS 264

// ---------------- device scratch ----------------
__device__ float g_csum[NC * DH];
__device__ int   g_cnt[NC];
__device__ int   g_off[NC];
__device__ int   g_perm[NMAX];
__device__ int   g_scid[NMAX];
__device__ __align__(16) __nv_bfloat16 g_w1bf[DH * DIN];

// ---------------- helpers ----------------
__device__ __forceinline__ uint32_t smem_to_u32(const void* p) {
    uint32_t a;
    asm("{ .reg .u64 t; cvta.to.shared.u64 t, %1; cvt.u32.u64 %0, t; }"
        : "=r"(a) : "l"(p));
    return a;
}
#define CP_ASYNC16(dst, src) \
    asm volatile("cp.async.cg.shared.global [%0], [%1], 16;" :: "r"(dst), "l"(src) : "memory")
#define CP_COMMIT() asm volatile("cp.async.commit_group;" ::: "memory")
#define CP_WAIT0()  asm volatile("cp.async.wait_group 0;" ::: "memory")
#define CP_WAIT1()  asm volatile("cp.async.wait_group 1;" ::: "memory")
#define LDSM4(r0, r1, r2, r3, a) \
    asm volatile("ldmatrix.sync.aligned.m8n8.x4.shared.b16 {%0,%1,%2,%3}, [%4];" \
                 : "=r"(r0), "=r"(r1), "=r"(r2), "=r"(r3) : "r"(a))
#define MMA16816(d0,d1,d2,d3, a0,a1,a2,a3, b0,b1) \
    asm volatile("mma.sync.aligned.m16n8k16.row.col.f32.bf16.bf16.f32 " \
                 "{%0,%1,%2,%3}, {%4,%5,%6,%7}, {%8,%9}, {%0,%1,%2,%3};\n" \
                 : "+f"(d0), "+f"(d1), "+f"(d2), "+f"(d3) \
                 : "r"(a0), "r"(a1), "r"(a2), "r"(a3), "r"(b0), "r"(b1))

// ---------------- k_prep: W1->bf16 (blocks 0..255) + cluster count (256..383) ----------------
__global__ void k_prep(const float* __restrict__ W1, const int* __restrict__ cid, int n) {
    if (blockIdx.x < 256) {
        int base = blockIdx.x * 1024 + threadIdx.x;
#pragma unroll
        for (int t = 0; t < 4; t++) {
            int i = base + t * 256;
            g_w1bf[i] = __float2bfloat16(W1[i]);
        }
    } else {
        __shared__ int h[NC];
        if (threadIdx.x < NC) h[threadIdx.x] = 0;
        __syncthreads();
        int b = blockIdx.x - 256;
        for (int i = b * 256 + threadIdx.x; i < n; i += 128 * 256)
            atomicAdd(&h[cid[i]], 1);
        __syncthreads();
        if (threadIdx.x < NC) atomicAdd(&g_cnt[threadIdx.x], h[threadIdx.x]);
    }
}

__global__ void k_prefix() {
    if (threadIdx.x == 0) {
        int s = 0;
        for (int c = 0; c < NC; c++) { g_off[c] = s; s += g_cnt[c]; }
    }
}

__global__ void k_scatter(const int* __restrict__ cid, int n) {
    __shared__ int lh[NC], base[NC], lr[NC];
    int i = blockIdx.x * 256 + threadIdx.x;
    int c = (i < n) ? cid[i] : -1;
    if (threadIdx.x < NC) { lh[threadIdx.x] = 0; lr[threadIdx.x] = 0; }
    __syncthreads();
    if (c >= 0) atomicAdd(&lh[c], 1);
    __syncthreads();
    if (threadIdx.x < NC && lh[threadIdx.x] > 0)
        base[threadIdx.x] = atomicAdd(&g_off[threadIdx.x], lh[threadIdx.x]);
    __syncthreads();
    if (c >= 0) {
        int r = atomicAdd(&lr[c], 1);
        int slot = base[c] + r;
        g_perm[slot] = i;
        g_scid[slot] = c;
    }
}

// ---------------- k_main: mma.sync GEMM + ReLU + segment-sum ----------------
// dynamic smem layout (bytes)
#define OFF_B1S  0          // 1024
#define OFF_CIDS 1024       // 512
#define OFF_PERM 1536       // 512
#define OFF_SPRT 2048       // NC*SPS*4 = 8448 -> ends 10496
#define OFF_A    12288      // 2 stages x 16384
#define OFF_B    45056      // 2 stages x 32768
#define A_STAGE  16384
#define B_STAGE  32768
#define SMEM_BYTES 110592

__global__ __launch_bounds__(NT, 1)
void k_main(const float* __restrict__ X, const float* __restrict__ b1, int n)
{
    extern __shared__ __align__(1024) char smem[];
    const uint32_t sb = smem_to_u32(smem);
    const int tid  = threadIdx.x;
    const int lane = tid & 31;
    const int wid  = tid >> 5;
    const int wm   = wid & 3;      // 4 warps along M (32 rows each)
    const int wn   = wid >> 2;     // 4 warps along N (64 cols each)
    const int rowBase = blockIdx.x * BM;

    float* b1s   = (float*)(smem + OFF_B1S);
    int*   cids  = (int*)(smem + OFF_CIDS);
    int*   perms = (int*)(smem + OFF_PERM);
    float* spart = (float*)(smem + OFF_SPRT);

    for (int i = tid; i < NC * SPS; i += NT) spart[i] = 0.f;
    if (tid < DH) b1s[tid] = b1[tid];
    if (tid < BM) {
        int g = rowBase + tid;
        perms[tid] = (g < n) ? g_perm[g] : 0;
        cids[tid]  = (g < n) ? g_scid[g] : 0;
    }
    __syncthreads();

    // ---- per-thread load maps ----
    const int xrow = tid >> 2;           // 0..127
    const int xseg = tid & 3;            // 16 floats each
    const bool xvalid = (rowBase + xrow) < n;
    const float* xsrc0 = X + (size_t)perms[xrow] * DIN + xseg * 16;
    const uint32_t xdst = sb + OFF_A + xrow * 128 +
                          ((xseg * 32) ^ ((xrow & 7) << 4));
    const uint32_t xdst2 = sb + OFF_A + xrow * 128 +
                           (((xseg * 32) + 16) ^ ((xrow & 7) << 4));

    const int wrow = tid >> 1;           // 0..255
    const int wseg = tid & 1;            // 32 elems each
    const __nv_bfloat16* wsrc0 = g_w1bf + (size_t)wrow * DIN + wseg * 32;
    uint32_t wdst[4];
#pragma unroll
    for (int q = 0; q < 4; q++)
        wdst[q] = sb + OFF_B + wrow * 128 +
                  ((wseg * 64 + q * 16) ^ ((wrow & 7) << 4));

    // ---- per-lane ldmatrix pointers ----
    uint32_t aPtr[2], bPtr[4];
    {
        int jm  = lane & 7;
        int sel8 = (lane >> 3) & 1;   // +8 rows
        int selk = (lane >> 4) & 1;   // k8..15
#pragma unroll
        for (int mt = 0; mt < 2; mt++) {
            int r = wm * 32 + mt * 16 + jm + sel8 * 8;
            aPtr[mt] = sb + OFF_A + r * 128 + ((selk * 16) ^ ((r & 7) << 4));
        }
        int jn  = lane & 7;
        int selk2 = (lane >> 3) & 1;  // k8..15
        int seln  = (lane >> 4) & 1;  // +8 n
#pragma unroll
        for (int p = 0; p < 4; p++) {
            int r = wn * 64 + p * 16 + jn + seln * 8;
            bPtr[p] = sb + OFF_B + r * 128 + ((selk2 * 16) ^ ((r & 7) << 4));
        }
    }

    float acc[2][8][4];
#pragma unroll
    for (int a = 0; a < 2; a++)
#pragma unroll
        for (int b = 0; b < 8; b++)
#pragma unroll
            for (int c = 0; c < 4; c++) acc[a][b][c] = 0.f;

    auto ldx = [&](int chunk, uint32_t h[8]) {
        float4 f[4];
        if (xvalid) {
            const float4* p = (const float4*)(xsrc0 + chunk * BK);
#pragma unroll
            for (int t = 0; t < 4; t++) f[t] = p[t];
        } else {
#pragma unroll
            for (int t = 0; t < 4; t++) f[t] = make_float4(0.f, 0.f, 0.f, 0.f);
        }
#pragma unroll
        for (int t = 0; t < 4; t++) {
            __nv_bfloat162 lo = __floats2bfloat162_rn(f[t].x, f[t].y);
            __nv_bfloat162 hi = __floats2bfloat162_rn(f[t].z, f[t].w);
            h[t * 2]     = *(uint32_t*)&lo;
            h[t * 2 + 1] = *(uint32_t*)&hi;
        }
    };
    auto stx = [&](int stage, const uint32_t h[8]) {
        uint32_t d0 = xdst + stage * A_STAGE, d1 = xdst2 + stage * A_STAGE;
        asm volatile("st.shared.v4.b32 [%0], {%1,%2,%3,%4};" ::
                     "r"(d0), "r"(h[0]), "r"(h[1]), "r"(h[2]), "r"(h[3]) : "memory");
        asm volatile("st.shared.v4.b32 [%0], {%1,%2,%3,%4};" ::
                     "r"(d1), "r"(h[4]), "r"(h[5]), "r"(h[6]), "r"(h[7]) : "memory");
    };
    auto ldw = [&](int chunk, int stage) {
        const char* s = (const char*)(wsrc0 + chunk * BK);
#pragma unroll
        for (int q = 0; q < 4; q++)
            CP_ASYNC16(wdst[q] + stage * B_STAGE, s + q * 16);
        CP_COMMIT();
    };

    auto compute = [&](int stage) {
        const uint32_t aOfs = stage * A_STAGE;
        const uint32_t bOfs = stage * B_STAGE;
#pragma unroll
        for (int kk = 0; kk < 4; kk++) {
            uint32_t af[2][4];
#pragma unroll
            for (int mt = 0; mt < 2; mt++)
                LDSM4(af[mt][0], af[mt][1], af[mt][2], af[mt][3],
                      (aPtr[mt] + aOfs) ^ (kk << 5));
            uint32_t bf[4][4];
#pragma unroll
            for (int p = 0; p < 4; p++)
                LDSM4(bf[p][0], bf[p][1], bf[p][2], bf[p][3],
                      (bPtr[p] + bOfs) ^ (kk << 5));
#pragma unroll
            for (int mt = 0; mt < 2; mt++)
#pragma unroll
                for (int p = 0; p < 4; p++) {
                    MMA16816(acc[mt][2*p][0],   acc[mt][2*p][1],
                             acc[mt][2*p][2],   acc[mt][2*p][3],
                             af[mt][0], af[mt][1], af[mt][2], af[mt][3],
                             bf[p][0], bf[p][1]);
                    MMA16816(acc[mt][2*p+1][0], acc[mt][2*p+1][1],
                             acc[mt][2*p+1][2], acc[mt][2*p+1][3],
                             af[mt][0], af[mt][1], af[mt][2], af[mt][3],
                             bf[p][2], bf[p][3]);
                }
        }
    };

    // ---- prologue: stage 0 filled ----
    {
        uint32_t h0[8];
        ldw(0, 0);          // cp.async group 0
        ldx(0, h0);
        stx(0, h0);
    }

    // ---- main loop: X latency hidden under compute ----
    uint32_t h2[8];
    for (int chunk = 0; chunk < CHUNKS; chunk++) {
        const int cur = chunk & 1;
        const int nxt = cur ^ 1;
        const bool more = (chunk + 1) < CHUNKS;
        if (more) {
            ldx(chunk + 1, h2);     // issue global loads now...
            ldw(chunk + 1, nxt);    // prefetch W into nxt stage
            CP_WAIT1();             // W(cur) arrived; W(nxt) stays in flight
        } else {
            CP_WAIT0();
        }
        __syncthreads();            // stx(cur) visible to all; prev compute done
        compute(cur);               // ...loads land while tensor pipe works
        if (more) {
            __syncthreads();        // everyone done reading nxt's previous data
            stx(nxt, h2);           // X data long since arrived
        }
    }

    // ---- epilogue: bias + ReLU + segment-sum ----
    const int g  = lane >> 2;
    const int tg = lane & 3;
    const bool uni = (cids[0] == cids[BM - 1]) && (rowBase + BM <= n);

    if (uni) {
        const int cl = cids[0];
#pragma unroll
        for (int nt = 0; nt < 8; nt++) {
            int c = wn * 64 + nt * 8 + tg * 2;
            float s0 = 0.f, s1 = 0.f;
#pragma unroll
            for (int mt = 0; mt < 2; mt++) {
                s0 += fmaxf(acc[mt][nt][0] + b1s[c], 0.f)
                    + fmaxf(acc[mt][nt][2] + b1s[c], 0.f);
                s1 += fmaxf(acc[mt][nt][1] + b1s[c + 1], 0.f)
                    + fmaxf(acc[mt][nt][3] + b1s[c + 1], 0.f);
            }
#pragma unroll
            for (int o = 4; o < 32; o <<= 1) {
                s0 += __shfl_xor_sync(0xffffffffu, s0, o);
                s1 += __shfl_xor_sync(0xffffffffu, s1, o);
            }
            if (g == 0) {
                atomicAdd(&spart[cl * SPS + c], s0);
                atomicAdd(&spart[cl * SPS + c + 1], s1);
            }
        }
    } else {
#pragma unroll
        for (int mt = 0; mt < 2; mt++) {
            int r0 = wm * 32 + mt * 16 + g;
            int r1 = r0 + 8;
            bool v0 = (rowBase + r0) < n;
            bool v1 = (rowBase + r1) < n;
            int c0 = cids[r0] * SPS;
            int c1 = cids[r1] * SPS;
#pragma unroll
            for (int nt = 0; nt < 8; nt++) {
                int c = wn * 64 + nt * 8 + tg * 2;
                float t;
                t = acc[mt][nt][0] + b1s[c];
                if (v0 && t > 0.f) atomicAdd(&spart[c0 + c], t);
                t = acc[mt][nt][1] + b1s[c + 1];
                if (v0 && t > 0.f) atomicAdd(&spart[c0 + c + 1], t);
                t = acc[mt][nt][2] + b1s[c];
                if (v1 && t > 0.f) atomicAdd(&spart[c1 + c], t);
                t = acc[mt][nt][3] + b1s[c + 1];
                if (v1 && t > 0.f) atomicAdd(&spart[c1 + c + 1], t);
            }
        }
    }
    __syncthreads();
    for (int i = tid; i < NC * DH; i += NT) {
        int c = i >> 8, j = i & 255;
        float v = spart[c * SPS + j];
        if (v != 0.f) atomicAdd(&g_csum[i], v);
    }
}

// ---------------- k_final: small MLP + gated attention ----------------
__global__ __launch_bounds__(512) void k_final(
    const float* __restrict__ Wf, const float* __restrict__ bfv,
    const float* __restrict__ Wa, const float* __restrict__ ba,
    const float* __restrict__ Wb, const float* __restrict__ bb,
    const float* __restrict__ Wc, const float* __restrict__ bc,
    float* __restrict__ out)
{
    __shared__ float hc[NC][DH];
    __shared__ float hp[NC][DH];
    __shared__ float pA[NC][DH];
    __shared__ float pB[NC][DH];
    __shared__ float asum[NC], wts[NC];

    const int tid = threadIdx.x;
    const int j = tid & 255;
    const int hf = tid >> 8;
    const int lane = tid & 31;

    for (int i = tid; i < NC * DH; i += 512) {
        int c = i >> 8;
        hc[c][i & 255] = g_csum[i] / fmaxf((float)g_cnt[c], 1.f);
    }
    if (tid < NC) asum[tid] = 0.f;
    __syncthreads();

    {
        float p[NC];
#pragma unroll
        for (int c = 0; c < NC; c++) p[c] = 0.f;
        const float4* wrow = (const float4*)(Wf + j * DH + hf * 128);
#pragma unroll 4
        for (int k4 = 0; k4 < 32; k4++) {
            float4 w = wrow[k4];
            int k = hf * 128 + k4 * 4;
#pragma unroll
            for (int c = 0; c < NC; c++) {
                float4 h4 = *(const float4*)&hc[c][k];
                p[c] += w.x * h4.x + w.y * h4.y + w.z * h4.z + w.w * h4.w;
            }
        }
        float* dst = hf ? &pB[0][0] : &pA[0][0];
#pragma unroll
        for (int c = 0; c < NC; c++) dst[c * DH + j] = p[c];
    }
    __syncthreads();

    float hpj[NC];
    if (hf == 0) {
#pragma unroll
        for (int c = 0; c < NC; c++) {
            hpj[c] = fmaxf(pA[c][j] + pB[c][j] + bfv[j], 0.f);
            hp[c][j] = hpj[c];
        }
    }
    __syncthreads();

    {
        const float* w2 = (hf ? Wb : Wa) + j * DH;
        float q[NC];
#pragma unroll
        for (int c = 0; c < NC; c++) q[c] = 0.f;
#pragma unroll 4
        for (int k4 = 0; k4 < 64; k4++) {
            float4 w = ((const float4*)w2)[k4];
#pragma unroll
            for (int c = 0; c < NC; c++) {
                float4 h4 = *(const float4*)&hp[c][k4 * 4];
                q[c] += w.x * h4.x + w.y * h4.y + w.z * h4.z + w.w * h4.w;
            }
        }
        float* dst = hf ? &pB[0][0] : &pA[0][0];
#pragma unroll
        for (int c = 0; c < NC; c++) dst[c * DH + j] = q[c];
    }
    __syncthreads();

    if (hf == 0) {
        float wcj = Wc[j];
#pragma unroll
        for (int c = 0; c < NC; c++) {
            float av = tanhf(pA[c][j] + ba[j]);
            float gv = 1.f / (1.f + __expf(-(pB[c][j] + bb[j])));
            float v = av * gv * wcj;
#pragma unroll
            for (int o = 16; o > 0; o >>= 1)
                v += __shfl_xor_sync(0xffffffffu, v, o);
            if (lane == 0) atomicAdd(&asum[c], v);
        }
    }
    __syncthreads();

    if (tid == 0) {
        float m = -1e30f;
        for (int c = 0; c < NC; c++) m = fmaxf(m, asum[c] + bc[0]);
        float s = 0.f;
        for (int c = 0; c < NC; c++) { wts[c] = __expf(asum[c] + bc[0] - m); s += wts[c]; }
        float inv = 1.f / s;
        for (int c = 0; c < NC; c++) wts[c] *= inv;
    }
    __syncthreads();

    if (hf == 0) {
        float s = 0.f;
#pragma unroll
        for (int c = 0; c < NC; c++) s += wts[c] * hpj[c];
        out[j] = s;
    }
}

// ---------------- launch ----------------
extern "C" void kernel_launch(void* const* d_in, const int* in_sizes, int n_in,
                              void* d_out, int out_size)
{
    const float* X   = (const float*)d_in[0];
    const int*   cid = (const int*)d_in[1];
    const float* W1  = (const float*)d_in[2];
    const float* b1  = (const float*)d_in[3];
    const float* Wf  = (const float*)d_in[4];
    const float* bfv = (const float*)d_in[5];
    const float* Wa  = (const float*)d_in[6];
    const float* ba  = (const float*)d_in[7];
    const float* Wb  = (const float*)d_in[8];
    const float* bb  = (const float*)d_in[9];
    const float* Wc  = (const float*)d_in[10];
    const float* bc  = (const float*)d_in[11];
    float* out = (float*)d_out;
    const int n = in_sizes[1];

    cudaFuncSetAttribute(k_main, cudaFuncAttributeMaxDynamicSharedMemorySize, SMEM_BYTES);

    void *p_csum = nullptr, *p_cnt = nullptr;
    cudaGetSymbolAddress(&p_csum, g_csum);
    cudaGetSymbolAddress(&p_cnt,  g_cnt);
    cudaMemsetAsync(p_csum, 0, sizeof(float) * NC * DH, 0);    // launch 1
    cudaMemsetAsync(p_cnt,  0, sizeof(int) * NC, 0);           // launch 2

    k_prep<<<384, 256>>>(W1, cid, n);                          // launch 3
    k_prefix<<<1, 32>>>();                                     // launch 4
    int sg = (n + 255) / 256;
    k_scatter<<<sg, 256>>>(cid, n);                            // launch 5

    int grid = (n + BM - 1) / BM;
    k_main<<<grid, NT, SMEM_BYTES>>>(X, b1, n);                // launch 6 (profiled)
    k_final<<<1, 512>>>(Wf, bfv, Wa, ba, Wb, bb, Wc, bc, out); // launch 7
}

// round 6
// speedup vs baseline: 1.4575x; 1.1284x over previous
#include <cuda_runtime.h>
#include <cuda_bf16.h>
#include <cstdint>

#define DIN 1024
#define DH  256
#define NC  8
#define NMAX 65536

#define BM 128          // rows per CTA
#define BNC 128         // cols per CTA
#define BK 64
#define NT 256
#define CHUNKS (DIN / BK)   // 16
#define STAGES 3
#define SPS 132

// ---------------- device scratch ----------------
__device__ float g_csum[NC * DH];
__device__ int   g_cnt[NC];
__device__ int   g_off[NC];
__device__ int   g_scid[NMAX];
__device__ __align__(16) __nv_bfloat16 g_w1bf[DH * DIN];
__device__ __align__(16) __nv_bfloat16 g_xbf[(size_t)NMAX * DIN];  // permuted bf16 X

// ---------------- helpers ----------------
__device__ __forceinline__ uint32_t smem_to_u32(const void* p) {
    uint32_t a;
    asm("{ .reg .u64 t; cvta.to.shared.u64 t, %1; cvt.u32.u64 %0, t; }"
        : "=r"(a) : "l"(p));
    return a;
}
#define CP_ASYNC16(dst, src) \
    asm volatile("cp.async.cg.shared.global [%0], [%1], 16;" :: "r"(dst), "l"(src) : "memory")
#define CP_COMMIT() asm volatile("cp.async.commit_group;" ::: "memory")
#define CP_WAITN(N) asm volatile("cp.async.wait_group %0;" :: "n"(N) : "memory")
#define LDSM4(r0, r1, r2, r3, a) \
    asm volatile("ldmatrix.sync.aligned.m8n8.x4.shared.b16 {%0,%1,%2,%3}, [%4];" \
                 : "=r"(r0), "=r"(r1), "=r"(r2), "=r"(r3) : "r"(a))
#define MMA16816(d0,d1,d2,d3, a0,a1,a2,a3, b0,b1) \
    asm volatile("mma.sync.aligned.m16n8k16.row.col.f32.bf16.bf16.f32 " \
                 "{%0,%1,%2,%3}, {%4,%5,%6,%7}, {%8,%9}, {%0,%1,%2,%3};\n" \
                 : "+f"(d0), "+f"(d1), "+f"(d2), "+f"(d3) \
                 : "r"(a0), "r"(a1), "r"(a2), "r"(a3), "r"(b0), "r"(b1))

// ---------------- k_prep: W1->bf16 (blocks 0..255) + cluster count (256..383) ----------------
__global__ void k_prep(const float* __restrict__ W1, const int* __restrict__ cid, int n) {
    if (blockIdx.x < 256) {
        int base = blockIdx.x * 1024 + threadIdx.x;
#pragma unroll
        for (int t = 0; t < 4; t++) {
            int i = base + t * 256;
            g_w1bf[i] = __float2bfloat16(W1[i]);
        }
    } else {
        __shared__ int h[NC];
        if (threadIdx.x < NC) h[threadIdx.x] = 0;
        __syncthreads();
        int b = blockIdx.x - 256;
        for (int i = b * 256 + threadIdx.x; i < n; i += 128 * 256)
            atomicAdd(&h[cid[i]], 1);
        __syncthreads();
        if (threadIdx.x < NC) atomicAdd(&g_cnt[threadIdx.x], h[threadIdx.x]);
    }
}

__global__ void k_prefix() {
    if (threadIdx.x == 0) {
        int s = 0;
        for (int c = 0; c < NC; c++) { g_off[c] = s; s += g_cnt[c]; }
    }
}

// ---------------- k_scatter: group rows by cluster AND convert X->bf16 permuted ----------------
#define SROWS 128
__global__ __launch_bounds__(256)
void k_scatter(const int* __restrict__ cid, const float* __restrict__ X, int n) {
    __shared__ int lh[NC], base[NC], lr[NC];
    __shared__ int slots[SROWS];
    const int tid = threadIdx.x;
    const int rb = blockIdx.x * SROWS;

    int c = -1;
    if (tid < SROWS) {
        int i = rb + tid;
        c = (i < n) ? cid[i] : -1;
    }
    if (tid < NC) { lh[tid] = 0; lr[tid] = 0; }
    __syncthreads();
    if (c >= 0) atomicAdd(&lh[c], 1);
    __syncthreads();
    if (tid < NC && lh[tid] > 0)
        base[tid] = atomicAdd(&g_off[tid], lh[tid]);
    __syncthreads();
    if (tid < SROWS) {
        if (c >= 0) {
            int r = atomicAdd(&lr[c], 1);
            int s = base[c] + r;
            slots[tid] = s;
            g_scid[s] = c;
        } else {
            slots[tid] = -1;
        }
    }
    __syncthreads();

    // copy + convert: row rb+r -> g_xbf[slots[r]]
    const int nrows = min(SROWS, n - rb);
#pragma unroll 4
    for (int r = 0; r < SROWS; r++) {
        if (r >= nrows) break;
        int s = slots[r];
        float4 f = ((const float4*)(X + (size_t)(rb + r) * DIN))[tid];
        __nv_bfloat162 lo = __floats2bfloat162_rn(f.x, f.y);
        __nv_bfloat162 hi = __floats2bfloat162_rn(f.z, f.w);
        uint2 v;
        v.x = *(uint32_t*)&lo;
        v.y = *(uint32_t*)&hi;
        *(uint2*)(g_xbf + (size_t)s * DIN + tid * 4) = v;
    }
}

// ---------------- k_main: cp.async 3-stage mma.sync GEMM + ReLU + segment-sum ----------------
// smem layout (bytes)
#define OFF_B1S  0          // 128 floats = 512
#define OFF_CIDS 512        // 128 ints = 512
#define OFF_SPRT 1024       // NC*SPS*4 = 4224 -> ends 5248
#define OFF_A    8192       // 3 stages x 16384
#define OFF_B    57344      // 3 stages x 16384
#define A_STAGE  16384
#define B_STAGE  16384
#define SMEM_BYTES 106496

__global__ __launch_bounds__(NT, 2)
void k_main(const float* __restrict__ b1, int n)
{
    extern __shared__ __align__(1024) char smem[];
    const uint32_t sb = smem_to_u32(smem);
    const int tid  = threadIdx.x;
    const int lane = tid & 31;
    const int wid  = tid >> 5;
    const int wm   = wid & 3;      // 4 warps along M (32 rows)
    const int wn   = wid >> 2;     // 2 warps along N (64 cols)
    const int rowBase = (blockIdx.x >> 1) * BM;
    const int colBase = (blockIdx.x & 1) * BNC;

    float* b1s   = (float*)(smem + OFF_B1S);
    int*   cids  = (int*)(smem + OFF_CIDS);
    float* spart = (float*)(smem + OFF_SPRT);

    for (int i = tid; i < NC * SPS; i += NT) spart[i] = 0.f;
    if (tid < BNC) b1s[tid] = b1[colBase + tid];
    if (tid < BM) {
        int g = rowBase + tid;
        cids[tid] = (g < n) ? g_scid[g] : 0;
    }

    // ---- cp.async source/dest maps: 4 units of 16B per thread per tile ----
    // unit u = i*NT + tid; row = u>>3, seg = u&7
    const char* aSrc[4];
    const char* bSrc[4];
    uint32_t aDst[4], bDst[4];
#pragma unroll
    for (int i = 0; i < 4; i++) {
        int u = i * NT + tid;
        int row = u >> 3, seg = u & 7;
        aSrc[i] = (const char*)(g_xbf + (size_t)(rowBase + row) * DIN + seg * 8);
        bSrc[i] = (const char*)(g_w1bf + (size_t)(colBase + row) * DIN + seg * 8);
        aDst[i] = sb + OFF_A + row * 128 + ((seg ^ (row & 7)) << 4);
        bDst[i] = sb + OFF_B + row * 128 + ((seg ^ (row & 7)) << 4);
    }

    auto issue = [&](int chunk) {
        const int st = chunk % STAGES;
        const int go = chunk * 128;   // bytes into the K dim (64 bf16)
#pragma unroll
        for (int i = 0; i < 4; i++)
            CP_ASYNC16(aDst[i] + st * A_STAGE, aSrc[i] + go);
#pragma unroll
        for (int i = 0; i < 4; i++)
            CP_ASYNC16(bDst[i] + st * B_STAGE, bSrc[i] + go);
        CP_COMMIT();
    };

    // ---- ldmatrix pointers ----
    uint32_t aPtr[2], bPtr[4];
    {
        int jm   = lane & 7;
        int sel8 = (lane >> 3) & 1;
        int selk = (lane >> 4) & 1;
#pragma unroll
        for (int mt = 0; mt < 2; mt++) {
            int r = wm * 32 + mt * 16 + jm + sel8 * 8;
            aPtr[mt] = sb + OFF_A + r * 128 + ((selk ^ (r & 7)) << 4);
        }
        int jn    = lane & 7;
        int selk2 = (lane >> 3) & 1;
        int seln  = (lane >> 4) & 1;
#pragma unroll
        for (int p = 0; p < 4; p++) {
            int r = wn * 64 + p * 16 + jn + seln * 8;
            bPtr[p] = sb + OFF_B + r * 128 + ((selk2 ^ (r & 7)) << 4);
        }
    }

    float acc[2][8][4];
#pragma unroll
    for (int a = 0; a < 2; a++)
#pragma unroll
        for (int b = 0; b < 8; b++)
#pragma unroll
            for (int c = 0; c < 4; c++) acc[a][b][c] = 0.f;

    auto compute = [&](int stage) {
        const uint32_t aOfs = stage * A_STAGE;
        const uint32_t bOfs = stage * B_STAGE;
#pragma unroll
        for (int kk = 0; kk < 4; kk++) {
            uint32_t af[2][4];
#pragma unroll
            for (int mt = 0; mt < 2; mt++)
                LDSM4(af[mt][0], af[mt][1], af[mt][2], af[mt][3],
                      (aPtr[mt] + aOfs) ^ (kk << 5));
            uint32_t bf[4][4];
#pragma unroll
            for (int p = 0; p < 4; p++)
                LDSM4(bf[p][0], bf[p][1], bf[p][2], bf[p][3],
                      (bPtr[p] + bOfs) ^ (kk << 5));
#pragma unroll
            for (int mt = 0; mt < 2; mt++)
#pragma unroll
                for (int p = 0; p < 4; p++) {
                    MMA16816(acc[mt][2*p][0],   acc[mt][2*p][1],
                             acc[mt][2*p][2],   acc[mt][2*p][3],
                             af[mt][0], af[mt][1], af[mt][2], af[mt][3],
                             bf[p][0], bf[p][1]);
                    MMA16816(acc[mt][2*p+1][0], acc[mt][2*p+1][1],
                             acc[mt][2*p+1][2], acc[mt][2*p+1][3],
                             af[mt][0], af[mt][1], af[mt][2], af[mt][3],
                             bf[p][2], bf[p][3]);
                }
        }
    };

    // ---- prologue: stages 0,1 in flight ----
    issue(0);
    issue(1);

    // ---- main loop: one barrier per chunk; loads run 2 chunks ahead ----
    for (int chunk = 0; chunk < CHUNKS; chunk++) {
        if (chunk + 2 < CHUNKS) CP_WAITN(1); else CP_WAITN(0);
        __syncthreads();
        if (chunk + 2 < CHUNKS) issue(chunk + 2);
        compute(chunk % STAGES);
    }

    // ---- epilogue: bias + ReLU + segment-sum ----
    const int g  = lane >> 2;
    const int tg = lane & 3;
    const bool uni = (cids[0] == cids[BM - 1]) && (rowBase + BM <= n);

    if (uni) {
        const int cl = cids[0];
#pragma unroll
        for (int nt = 0; nt < 8; nt++) {
            int c = wn * 64 + nt * 8 + tg * 2;
            float s0 = 0.f, s1 = 0.f;
#pragma unroll
            for (int mt = 0; mt < 2; mt++) {
                s0 += fmaxf(acc[mt][nt][0] + b1s[c], 0.f)
                    + fmaxf(acc[mt][nt][2] + b1s[c], 0.f);
                s1 += fmaxf(acc[mt][nt][1] + b1s[c + 1], 0.f)
                    + fmaxf(acc[mt][nt][3] + b1s[c + 1], 0.f);
            }
#pragma unroll
            for (int o = 4; o < 32; o <<= 1) {
                s0 += __shfl_xor_sync(0xffffffffu, s0, o);
                s1 += __shfl_xor_sync(0xffffffffu, s1, o);
            }
            if (g == 0) {
                atomicAdd(&spart[cl * SPS + c], s0);
                atomicAdd(&spart[cl * SPS + c + 1], s1);
            }
        }
    } else {
#pragma unroll
        for (int mt = 0; mt < 2; mt++) {
            int r0 = wm * 32 + mt * 16 + g;
            int r1 = r0 + 8;
            bool v0 = (rowBase + r0) < n;
            bool v1 = (rowBase + r1) < n;
            int c0 = cids[r0] * SPS;
            int c1 = cids[r1] * SPS;
#pragma unroll
            for (int nt = 0; nt < 8; nt++) {
                int c = wn * 64 + nt * 8 + tg * 2;
                float t;
                t = acc[mt][nt][0] + b1s[c];
                if (v0 && t > 0.f) atomicAdd(&spart[c0 + c], t);
                t = acc[mt][nt][1] + b1s[c + 1];
                if (v0 && t > 0.f) atomicAdd(&spart[c0 + c + 1], t);
                t = acc[mt][nt][2] + b1s[c];
                if (v1 && t > 0.f) atomicAdd(&spart[c1 + c], t);
                t = acc[mt][nt][3] + b1s[c + 1];
                if (v1 && t > 0.f) atomicAdd(&spart[c1 + c + 1], t);
            }
        }
    }
    __syncthreads();
    for (int i = tid; i < NC * BNC; i += NT) {
        int c = i >> 7, j = i & 127;
        float v = spart[c * SPS + j];
        if (v != 0.f) atomicAdd(&g_csum[c * DH + colBase + j], v);
    }
}

// ---------------- k_final: small MLP + gated attention ----------------
__global__ __launch_bounds__(512) void k_final(
    const float* __restrict__ Wf, const float* __restrict__ bfv,
    const float* __restrict__ Wa, const float* __restrict__ ba,
    const float* __restrict__ Wb, const float* __restrict__ bb,
    const float* __restrict__ Wc, const float* __restrict__ bc,
    float* __restrict__ out)
{
    __shared__ float hc[NC][DH];
    __shared__ float hp[NC][DH];
    __shared__ float pA[NC][DH];
    __shared__ float pB[NC][DH];
    __shared__ float asum[NC], wts[NC];

    const int tid = threadIdx.x;
    const int j = tid & 255;
    const int hf = tid >> 8;
    const int lane = tid & 31;

    for (int i = tid; i < NC * DH; i += 512) {
        int c = i >> 8;
        hc[c][i & 255] = g_csum[i] / fmaxf((float)g_cnt[c], 1.f);
    }
    if (tid < NC) asum[tid] = 0.f;
    __syncthreads();

    {
        float p[NC];
#pragma unroll
        for (int c = 0; c < NC; c++) p[c] = 0.f;
        const float4* wrow = (const float4*)(Wf + j * DH + hf * 128);
#pragma unroll 4
        for (int k4 = 0; k4 < 32; k4++) {
            float4 w = wrow[k4];
            int k = hf * 128 + k4 * 4;
#pragma unroll
            for (int c = 0; c < NC; c++) {
                float4 h4 = *(const float4*)&hc[c][k];
                p[c] += w.x * h4.x + w.y * h4.y + w.z * h4.z + w.w * h4.w;
            }
        }
        float* dst = hf ? &pB[0][0] : &pA[0][0];
#pragma unroll
        for (int c = 0; c < NC; c++) dst[c * DH + j] = p[c];
    }
    __syncthreads();

    float hpj[NC];
    if (hf == 0) {
#pragma unroll
        for (int c = 0; c < NC; c++) {
            hpj[c] = fmaxf(pA[c][j] + pB[c][j] + bfv[j], 0.f);
            hp[c][j] = hpj[c];
        }
    }
    __syncthreads();

    {
        const float* w2 = (hf ? Wb : Wa) + j * DH;
        float q[NC];
#pragma unroll
        for (int c = 0; c < NC; c++) q[c] = 0.f;
#pragma unroll 4
        for (int k4 = 0; k4 < 64; k4++) {
            float4 w = ((const float4*)w2)[k4];
#pragma unroll
            for (int c = 0; c < NC; c++) {
                float4 h4 = *(const float4*)&hp[c][k4 * 4];
                q[c] += w.x * h4.x + w.y * h4.y + w.z * h4.z + w.w * h4.w;
            }
        }
        float* dst = hf ? &pB[0][0] : &pA[0][0];
#pragma unroll
        for (int c = 0; c < NC; c++) dst[c * DH + j] = q[c];
    }
    __syncthreads();

    if (hf == 0) {
        float wcj = Wc[j];
#pragma unroll
        for (int c = 0; c < NC; c++) {
            float av = tanhf(pA[c][j] + ba[j]);
            float gv = 1.f / (1.f + __expf(-(pB[c][j] + bb[j])));
            float v = av * gv * wcj;
#pragma unroll
            for (int o = 16; o > 0; o >>= 1)
                v += __shfl_xor_sync(0xffffffffu, v, o);
            if (lane == 0) atomicAdd(&asum[c], v);
        }
    }
    __syncthreads();

    if (tid == 0) {
        float m = -1e30f;
        for (int c = 0; c < NC; c++) m = fmaxf(m, asum[c] + bc[0]);
        float s = 0.f;
        for (int c = 0; c < NC; c++) { wts[c] = __expf(asum[c] + bc[0] - m); s += wts[c]; }
        float inv = 1.f / s;
        for (int c = 0; c < NC; c++) wts[c] *= inv;
    }
    __syncthreads();

    if (hf == 0) {
        float s = 0.f;
#pragma unroll
        for (int c = 0; c < NC; c++) s += wts[c] * hpj[c];
        out[j] = s;
    }
}

// ---------------- launch ----------------
extern "C" void kernel_launch(void* const* d_in, const int* in_sizes, int n_in,
                              void* d_out, int out_size)
{
    const float* X   = (const float*)d_in[0];
    const int*   cid = (const int*)d_in[1];
    const float* W1  = (const float*)d_in[2];
    const float* b1  = (const float*)d_in[3];
    const float* Wf  = (const float*)d_in[4];
    const float* bfv = (const float*)d_in[5];
    const float* Wa  = (const float*)d_in[6];
    const float* ba  = (const float*)d_in[7];
    const float* Wb  = (const float*)d_in[8];
    const float* bb  = (const float*)d_in[9];
    const float* Wc  = (const float*)d_in[10];
    const float* bc  = (const float*)d_in[11];
    float* out = (float*)d_out;
    const int n = in_sizes[1];

    cudaFuncSetAttribute(k_main, cudaFuncAttributeMaxDynamicSharedMemorySize, SMEM_BYTES);

    void *p_csum = nullptr, *p_cnt = nullptr;
    cudaGetSymbolAddress(&p_csum, g_csum);
    cudaGetSymbolAddress(&p_cnt,  g_cnt);
    cudaMemsetAsync(p_csum, 0, sizeof(float) * NC * DH, 0);     // launch 1
    cudaMemsetAsync(p_cnt,  0, sizeof(int) * NC, 0);            // launch 2

    k_prep<<<384, 256>>>(W1, cid, n);                           // launch 3
    k_prefix<<<1, 32>>>();                                      // launch 4
    int sg = (n + SROWS - 1) / SROWS;
    k_scatter<<<sg, 256>>>(cid, X, n);                          // launch 5

    int grid = ((n + BM - 1) / BM) * 2;
    k_main<<<grid, NT, SMEM_BYTES>>>(b1, n);                    // launch 6 (profiled)
    k_final<<<1, 512>>>(Wf, bfv, Wa, ba, Wb, bb, Wc, bc, out);  // launch 7
}

// round 7
// speedup vs baseline: 1.5610x; 1.0710x over previous
#include <cuda_runtime.h>
#include <cuda_bf16.h>
#include <cstdint>

#define DIN 1024
#define DH  256
#define NC  8
#define NMAX 65536

#define BM 128          // rows per CTA
#define BNC 128         // cols per CTA
#define BK 64
#define NT 256
#define CHUNKS (DIN / BK)   // 16
#define SPS 132

// ---------------- device scratch ----------------
__device__ float g_csum[NC * DH];
__device__ int   g_cnt[NC];
__device__ int   g_off[NC];
__device__ int   g_perm[NMAX];
__device__ int   g_scid[NMAX];
__device__ __align__(16) __nv_bfloat16 g_w1bf[DH * DIN];

// ---------------- helpers ----------------
__device__ __forceinline__ uint32_t smem_to_u32(const void* p) {
    uint32_t a;
    asm("{ .reg .u64 t; cvta.to.shared.u64 t, %1; cvt.u32.u64 %0, t; }"
        : "=r"(a) : "l"(p));
    return a;
}
#define CP_ASYNC16(dst, src) \
    asm volatile("cp.async.cg.shared.global [%0], [%1], 16;" :: "r"(dst), "l"(src) : "memory")
#define CP_COMMIT() asm volatile("cp.async.commit_group;" ::: "memory")
#define CP_WAIT0()  asm volatile("cp.async.wait_group 0;" ::: "memory")
#define LDSM4(r0, r1, r2, r3, a) \
    asm volatile("ldmatrix.sync.aligned.m8n8.x4.shared.b16 {%0,%1,%2,%3}, [%4];" \
                 : "=r"(r0), "=r"(r1), "=r"(r2), "=r"(r3) : "r"(a))
#define MMA16816(d0,d1,d2,d3, a0,a1,a2,a3, b0,b1) \
    asm volatile("mma.sync.aligned.m16n8k16.row.col.f32.bf16.bf16.f32 " \
                 "{%0,%1,%2,%3}, {%4,%5,%6,%7}, {%8,%9}, {%0,%1,%2,%3};\n" \
                 : "+f"(d0), "+f"(d1), "+f"(d2), "+f"(d3) \
                 : "r"(a0), "r"(a1), "r"(a2), "r"(a3), "r"(b0), "r"(b1))

// ---------------- k_prep: W1->bf16 (blocks 0..255) + cluster count (256..383) ----------------
__global__ void k_prep(const float* __restrict__ W1, const int* __restrict__ cid, int n) {
    if (blockIdx.x < 256) {
        int base = blockIdx.x * 1024 + threadIdx.x;
#pragma unroll
        for (int t = 0; t < 4; t++) {
            int i = base + t * 256;
            g_w1bf[i] = __float2bfloat16(W1[i]);
        }
    } else {
        __shared__ int h[NC];
        if (threadIdx.x < NC) h[threadIdx.x] = 0;
        __syncthreads();
        int b = blockIdx.x - 256;
        for (int i = b * 256 + threadIdx.x; i < n; i += 128 * 256)
            atomicAdd(&h[cid[i]], 1);
        __syncthreads();
        if (threadIdx.x < NC) atomicAdd(&g_cnt[threadIdx.x], h[threadIdx.x]);
    }
}

__global__ void k_prefix() {
    if (threadIdx.x == 0) {
        int s = 0;
        for (int c = 0; c < NC; c++) { g_off[c] = s; s += g_cnt[c]; }
    }
}

// ---------------- k_scatter: permutation indices only (no data copy) ----------------
__global__ __launch_bounds__(128)
void k_scatter(const int* __restrict__ cid, int n) {
    __shared__ int lh[NC], base[NC], lr[NC];
    const int tid = threadIdx.x;
    int i = blockIdx.x * 128 + tid;
    int c = (i < n) ? cid[i] : -1;
    if (tid < NC) { lh[tid] = 0; lr[tid] = 0; }
    __syncthreads();
    if (c >= 0) atomicAdd(&lh[c], 1);
    __syncthreads();
    if (tid < NC && lh[tid] > 0)
        base[tid] = atomicAdd(&g_off[tid], lh[tid]);
    __syncthreads();
    if (c >= 0) {
        int r = atomicAdd(&lr[c], 1);
        int s = base[c] + r;
        g_perm[s] = i;
        g_scid[s] = c;
    }
}

// ---------------- k_main: gather fp32 X + in-pipeline convert + mma.sync + segment-sum ----------------
// smem layout (bytes)
#define OFF_B1S  0          // 128 floats = 512
#define OFF_CIDS 512        // 128 ints
#define OFF_PERM 1024       // 128 ints
#define OFF_SPRT 1536       // NC*SPS*4 = 4224 -> ends 5760
#define OFF_AF32 8192       // fp32 staging: 128 rows x 288B = 36864 -> ends 45056
#define AF32_ROW 288
#define OFF_A    45056      // bf16 A: 2 stages x 16384 -> ends 77824
#define OFF_B    77824      // bf16 B: 2 stages x 16384 -> ends 110592
#define A_STAGE  16384
#define B_STAGE  16384
#define SMEM_BYTES 110592

__global__ __launch_bounds__(NT, 2)
void k_main(const float* __restrict__ X, const float* __restrict__ b1, int n)
{
    extern __shared__ __align__(1024) char smem[];
    const uint32_t sb = smem_to_u32(smem);
    const int tid  = threadIdx.x;
    const int lane = tid & 31;
    const int wid  = tid >> 5;
    const int wm   = wid & 3;      // 4 warps along M (32 rows)
    const int wn   = wid >> 2;     // 2 warps along N (64 cols)
    const int rowBase = (blockIdx.x >> 1) * BM;
    const int colBase = (blockIdx.x & 1) * BNC;

    float* b1s   = (float*)(smem + OFF_B1S);
    int*   cids  = (int*)(smem + OFF_CIDS);
    int*   perms = (int*)(smem + OFF_PERM);
    float* spart = (float*)(smem + OFF_SPRT);

    for (int i = tid; i < NC * SPS; i += NT) spart[i] = 0.f;
    if (tid < BNC) b1s[tid] = b1[colBase + tid];
    if (tid < BM) {
        int g = rowBase + tid;
        int ok = (g < n);
        perms[tid] = ok ? g_perm[g] : 0;
        cids[tid]  = ok ? g_scid[g] : 0;
    }
    __syncthreads();

    // ---- B cp.async maps: 4 units of 16B per thread ----
    const char* bSrc[4];
    uint32_t bDst[4];
#pragma unroll
    for (int i = 0; i < 4; i++) {
        int u = i * NT + tid;
        int row = u >> 3, seg = u & 7;
        bSrc[i] = (const char*)(g_w1bf + (size_t)(colBase + row) * DIN + seg * 8);
        bDst[i] = sb + OFF_B + row * 128 + ((seg ^ (row & 7)) << 4);
    }

    // A issue: 8 units of 16B per thread into fp32 staging
    auto issueA = [&](int chunk) {
        const int go = chunk * 256;   // byte offset into X row (64 floats)
#pragma unroll
        for (int i = 0; i < 8; i++) {
            int u = i * NT + tid;
            int row = u >> 4, seg16 = u & 15;
            int half = seg16 >> 3, j = seg16 & 7;
            const char* src = (const char*)X +
                ((size_t)perms[row] * DIN + seg16 * 4) * 4 + go;
            uint32_t dst = sb + OFF_AF32 + row * AF32_ROW + half * 144 + j * 16;
            CP_ASYNC16(dst, src);
        }
    };
    auto issueB = [&](int chunk, int st) {
        const int go = chunk * 128;
#pragma unroll
        for (int i = 0; i < 4; i++)
            CP_ASYNC16(bDst[i] + st * B_STAGE, bSrc[i] + go);
    };

    // ---- convert: fp32 staging -> bf16 A tile (thread: row=tid>>1, half=tid&1) ----
    const int cvrow  = tid >> 1;
    const int cvhalf = tid & 1;
    const uint32_t cvSrc = sb + OFF_AF32 + cvrow * AF32_ROW + cvhalf * 144;
    uint32_t cvDst[4];
#pragma unroll
    for (int q = 0; q < 4; q++)
        cvDst[q] = sb + OFF_A + cvrow * 128 +
                   (((cvhalf * 4 + q) ^ (cvrow & 7)) << 4);

    auto convertA = [&](int st) {
        float f[32];
#pragma unroll
        for (int t = 0; t < 8; t++)
            asm volatile("ld.shared.v4.f32 {%0,%1,%2,%3}, [%4];"
                : "=f"(f[t*4]), "=f"(f[t*4+1]), "=f"(f[t*4+2]), "=f"(f[t*4+3])
                : "r"(cvSrc + t * 16));
#pragma unroll
        for (int q = 0; q < 4; q++) {
            uint32_t v[4];
#pragma unroll
            for (int p = 0; p < 4; p++) {
                __nv_bfloat162 b2 = __floats2bfloat162_rn(f[q*8 + p*2], f[q*8 + p*2 + 1]);
                v[p] = *(uint32_t*)&b2;
            }
            asm volatile("st.shared.v4.b32 [%0], {%1,%2,%3,%4};" ::
                "r"(cvDst[q] + st * A_STAGE),
                "r"(v[0]), "r"(v[1]), "r"(v[2]), "r"(v[3]) : "memory");
        }
    };

    // ---- ldmatrix pointers ----
    uint32_t aPtr[2], bPtr[4];
    {
        int jm   = lane & 7;
        int sel8 = (lane >> 3) & 1;
        int selk = (lane >> 4) & 1;
#pragma unroll
        for (int mt = 0; mt < 2; mt++) {
            int r = wm * 32 + mt * 16 + jm + sel8 * 8;
            aPtr[mt] = sb + OFF_A + r * 128 + ((selk ^ (r & 7)) << 4);
        }
        int jn    = lane & 7;
        int selk2 = (lane >> 3) & 1;
        int seln  = (lane >> 4) & 1;
#pragma unroll
        for (int p = 0; p < 4; p++) {
            int r = wn * 64 + p * 16 + jn + seln * 8;
            bPtr[p] = sb + OFF_B + r * 128 + ((selk2 ^ (r & 7)) << 4);
        }
    }

    float acc[2][8][4];
#pragma unroll
    for (int a = 0; a < 2; a++)
#pragma unroll
        for (int b = 0; b < 8; b++)
#pragma unroll
            for (int c = 0; c < 4; c++) acc[a][b][c] = 0.f;

    auto compute = [&](int stage) {
        const uint32_t aOfs = stage * A_STAGE;
        const uint32_t bOfs = stage * B_STAGE;
#pragma unroll
        for (int kk = 0; kk < 4; kk++) {
            uint32_t af[2][4];
#pragma unroll
            for (int mt = 0; mt < 2; mt++)
                LDSM4(af[mt][0], af[mt][1], af[mt][2], af[mt][3],
                      (aPtr[mt] + aOfs) ^ (kk << 5));
            uint32_t bf[4][4];
#pragma unroll
            for (int p = 0; p < 4; p++)
                LDSM4(bf[p][0], bf[p][1], bf[p][2], bf[p][3],
                      (bPtr[p] + bOfs) ^ (kk << 5));
#pragma unroll
            for (int mt = 0; mt < 2; mt++)
#pragma unroll
                for (int p = 0; p < 4; p++) {
                    MMA16816(acc[mt][2*p][0],   acc[mt][2*p][1],
                             acc[mt][2*p][2],   acc[mt][2*p][3],
                             af[mt][0], af[mt][1], af[mt][2], af[mt][3],
                             bf[p][0], bf[p][1]);
                    MMA16816(acc[mt][2*p+1][0], acc[mt][2*p+1][1],
                             acc[mt][2*p+1][2], acc[mt][2*p+1][3],
                             af[mt][0], af[mt][1], af[mt][2], af[mt][3],
                             bf[p][2], bf[p][3]);
                }
        }
    };

    // ---- prologue: chunk 0 in flight ----
    issueA(0);
    issueB(0, 0);
    CP_COMMIT();

    // ---- main loop ----
    for (int chunk = 0; chunk < CHUNKS; chunk++) {
        const int st = chunk & 1;
        CP_WAIT0();
        __syncthreads();           // staging + B(st) ready; prev compute done
        convertA(st);
        __syncthreads();           // bf16 A(st) visible; staging free
        if (chunk + 1 < CHUNKS) {
            issueA(chunk + 1);
            issueB(chunk + 1, st ^ 1);
            CP_COMMIT();
        }
        compute(st);               // loads land under the MMA shadow
    }

    // ---- epilogue: bias + ReLU + segment-sum ----
    const int g  = lane >> 2;
    const int tg = lane & 3;
    const bool uni = (cids[0] == cids[BM - 1]) && (rowBase + BM <= n);

    if (uni) {
        const int cl = cids[0];
#pragma unroll
        for (int nt = 0; nt < 8; nt++) {
            int c = wn * 64 + nt * 8 + tg * 2;
            float s0 = 0.f, s1 = 0.f;
#pragma unroll
            for (int mt = 0; mt < 2; mt++) {
                s0 += fmaxf(acc[mt][nt][0] + b1s[c], 0.f)
                    + fmaxf(acc[mt][nt][2] + b1s[c], 0.f);
                s1 += fmaxf(acc[mt][nt][1] + b1s[c + 1], 0.f)
                    + fmaxf(acc[mt][nt][3] + b1s[c + 1], 0.f);
            }
#pragma unroll
            for (int o = 4; o < 32; o <<= 1) {
                s0 += __shfl_xor_sync(0xffffffffu, s0, o);
                s1 += __shfl_xor_sync(0xffffffffu, s1, o);
            }
            if (g == 0) {
                atomicAdd(&spart[cl * SPS + c], s0);
                atomicAdd(&spart[cl * SPS + c + 1], s1);
            }
        }
    } else {
#pragma unroll
        for (int mt = 0; mt < 2; mt++) {
            int r0 = wm * 32 + mt * 16 + g;
            int r1 = r0 + 8;
            bool v0 = (rowBase + r0) < n;
            bool v1 = (rowBase + r1) < n;
            int c0 = cids[r0] * SPS;
            int c1 = cids[r1] * SPS;
#pragma unroll
            for (int nt = 0; nt < 8; nt++) {
                int c = wn * 64 + nt * 8 + tg * 2;
                float t;
                t = acc[mt][nt][0] + b1s[c];
                if (v0 && t > 0.f) atomicAdd(&spart[c0 + c], t);
                t = acc[mt][nt][1] + b1s[c + 1];
                if (v0 && t > 0.f) atomicAdd(&spart[c0 + c + 1], t);
                t = acc[mt][nt][2] + b1s[c];
                if (v1 && t > 0.f) atomicAdd(&spart[c1 + c], t);
                t = acc[mt][nt][3] + b1s[c + 1];
                if (v1 && t > 0.f) atomicAdd(&spart[c1 + c + 1], t);
            }
        }
    }
    __syncthreads();
    for (int i = tid; i < NC * BNC; i += NT) {
        int c = i >> 7, j = i & 127;
        float v = spart[c * SPS + j];
        if (v != 0.f) atomicAdd(&g_csum[c * DH + colBase + j], v);
    }
}

// ---------------- k_final: small MLP + gated attention ----------------
__global__ __launch_bounds__(512) void k_final(
    const float* __restrict__ Wf, const float* __restrict__ bfv,
    const float* __restrict__ Wa, const float* __restrict__ ba,
    const float* __restrict__ Wb, const float* __restrict__ bb,
    const float* __restrict__ Wc, const float* __restrict__ bc,
    float* __restrict__ out)
{
    __shared__ float hc[NC][DH];
    __shared__ float hp[NC][DH];
    __shared__ float pA[NC][DH];
    __shared__ float pB[NC][DH];
    __shared__ float asum[NC], wts[NC];

    const int tid = threadIdx.x;
    const int j = tid & 255;
    const int hf = tid >> 8;
    const int lane = tid & 31;

    for (int i = tid; i < NC * DH; i += 512) {
        int c = i >> 8;
        hc[c][i & 255] = g_csum[i] / fmaxf((float)g_cnt[c], 1.f);
    }
    if (tid < NC) asum[tid] = 0.f;
    __syncthreads();

    {
        float p[NC];
#pragma unroll
        for (int c = 0; c < NC; c++) p[c] = 0.f;
        const float4* wrow = (const float4*)(Wf + j * DH + hf * 128);
#pragma unroll 4
        for (int k4 = 0; k4 < 32; k4++) {
            float4 w = wrow[k4];
            int k = hf * 128 + k4 * 4;
#pragma unroll
            for (int c = 0; c < NC; c++) {
                float4 h4 = *(const float4*)&hc[c][k];
                p[c] += w.x * h4.x + w.y * h4.y + w.z * h4.z + w.w * h4.w;
            }
        }
        float* dst = hf ? &pB[0][0] : &pA[0][0];
#pragma unroll
        for (int c = 0; c < NC; c++) dst[c * DH + j] = p[c];
    }
    __syncthreads();

    float hpj[NC];
    if (hf == 0) {
#pragma unroll
        for (int c = 0; c < NC; c++) {
            hpj[c] = fmaxf(pA[c][j] + pB[c][j] + bfv[j], 0.f);
            hp[c][j] = hpj[c];
        }
    }
    __syncthreads();

    {
        const float* w2 = (hf ? Wb : Wa) + j * DH;
        float q[NC];
#pragma unroll
        for (int c = 0; c < NC; c++) q[c] = 0.f;
#pragma unroll 4
        for (int k4 = 0; k4 < 64; k4++) {
            float4 w = ((const float4*)w2)[k4];
#pragma unroll
            for (int c = 0; c < NC; c++) {
                float4 h4 = *(const float4*)&hp[c][k4 * 4];
                q[c] += w.x * h4.x + w.y * h4.y + w.z * h4.z + w.w * h4.w;
            }
        }
        float* dst = hf ? &pB[0][0] : &pA[0][0];
#pragma unroll
        for (int c = 0; c < NC; c++) dst[c * DH + j] = q[c];
    }
    __syncthreads();

    if (hf == 0) {
        float wcj = Wc[j];
#pragma unroll
        for (int c = 0; c < NC; c++) {
            float av = tanhf(pA[c][j] + ba[j]);
            float gv = 1.f / (1.f + __expf(-(pB[c][j] + bb[j])));
            float v = av * gv * wcj;
#pragma unroll
            for (int o = 16; o > 0; o >>= 1)
                v += __shfl_xor_sync(0xffffffffu, v, o);
            if (lane == 0) atomicAdd(&asum[c], v);
        }
    }
    __syncthreads();

    if (tid == 0) {
        float m = -1e30f;
        for (int c = 0; c < NC; c++) m = fmaxf(m, asum[c] + bc[0]);
        float s = 0.f;
        for (int c = 0; c < NC; c++) { wts[c] = __expf(asum[c] + bc[0] - m); s += wts[c]; }
        float inv = 1.f / s;
        for (int c = 0; c < NC; c++) wts[c] *= inv;
    }
    __syncthreads();

    if (hf == 0) {
        float s = 0.f;
#pragma unroll
        for (int c = 0; c < NC; c++) s += wts[c] * hpj[c];
        out[j] = s;
    }
}

// ---------------- launch ----------------
extern "C" void kernel_launch(void* const* d_in, const int* in_sizes, int n_in,
                              void* d_out, int out_size)
{
    const float* X   = (const float*)d_in[0];
    const int*   cid = (const int*)d_in[1];
    const float* W1  = (const float*)d_in[2];
    const float* b1  = (const float*)d_in[3];
    const float* Wf  = (const float*)d_in[4];
    const float* bfv = (const float*)d_in[5];
    const float* Wa  = (const float*)d_in[6];
    const float* ba  = (const float*)d_in[7];
    const float* Wb  = (const float*)d_in[8];
    const float* bb  = (const float*)d_in[9];
    const float* Wc  = (const float*)d_in[10];
    const float* bc  = (const float*)d_in[11];
    float* out = (float*)d_out;
    const int n = in_sizes[1];

    cudaFuncSetAttribute(k_main, cudaFuncAttributeMaxDynamicSharedMemorySize, SMEM_BYTES);

    void *p_csum = nullptr, *p_cnt = nullptr;
    cudaGetSymbolAddress(&p_csum, g_csum);
    cudaGetSymbolAddress(&p_cnt,  g_cnt);
    cudaMemsetAsync(p_csum, 0, sizeof(float) * NC * DH, 0);     // launch 1
    cudaMemsetAsync(p_cnt,  0, sizeof(int) * NC, 0);            // launch 2

    k_prep<<<384, 256>>>(W1, cid, n);                           // launch 3
    k_prefix<<<1, 32>>>();                                      // launch 4
    int sg = (n + 127) / 128;
    k_scatter<<<sg, 128>>>(cid, n);                             // launch 5

    int grid = ((n + BM - 1) / BM) * 2;
    k_main<<<grid, NT, SMEM_BYTES>>>(X, b1, n);                 // launch 6 (profiled)
    k_final<<<1, 512>>>(Wf, bfv, Wa, ba, Wb, bb, Wc, bc, out);  // launch 7
}